// round 14
// baseline (speedup 1.0000x reference)
#include <cuda_runtime.h>
#include <cuda_fp16.h>
#include <math.h>

#define LSEQ 65536
#define NS   100
#define S2   200
#define XD   300
#define G4   400
#define NV   128
#define NB   148
#define NT   2048
#define MAXT 14
#define LOG2E 1.4426950408889634f

// dynamic smem layout (bytes)
#define OFF_IMC8 0
#define OFF_W18  (MAXT * 6400)                 // 89600
#define OFF_W2HT (OFF_W18 + MAXT * 3200)       // 134400
#define OFF_WH2  (OFF_W2HT + 40000)            // 174400
#define DYN_SZ   (OFF_WH2 + 16 * 104 * 4)      // 181056

// ---------------- device scratch ----------------
__device__ __align__(128) __half2 g_imc [LSEQ * 100];        // fp16 [l][j2] (precompute input)
__device__ __align__(128) unsigned char g_imc8[LSEQ * 200];  // fp8 [l][j]
__device__ __align__(128) unsigned char g_w1t8[NT * 3200];   // fp8 [tile][a4][lane] uints
__device__ float g_w1T[S2 * NS];
__device__ float g_expC;
__device__ __align__(16) float g_ctxbuf[2][256];             // double-buffered; [200]=Z
__device__ __align__(16) float g_gate[G4];
__device__ __align__(128) unsigned g_flags[NB * 8];          // monotonic wave tags
__device__ unsigned g_rsvd;

// ---------------- helpers ----------------
__device__ __forceinline__ float ex2fast(float x) {
    float y; asm("ex2.approx.f32 %0, %1;" : "=f"(y) : "f"(x)); return y;
}
__device__ __forceinline__ __half2 tanh2(__half2 x) {
    unsigned xi = *(unsigned*)&x, yi;
    asm("tanh.approx.f16x2 %0, %1;" : "=r"(yi) : "r"(xi));
    return *(__half2*)&yi;
}
__device__ __forceinline__ float sigf(float x) {
    float t; asm("ex2.approx.f32 %0, %1;" : "=f"(t) : "f"(-x * LOG2E));
    float r; asm("rcp.approx.f32 %0, %1;" : "=f"(r) : "f"(1.f + t));
    return r;
}
__device__ __forceinline__ float tanh_acc(float x) {
    x = fminf(10.f, fmaxf(-10.f, x));
    float t; asm("ex2.approx.f32 %0, %1;" : "=f"(t) : "f"(x * 2.885390081777927f));
    float r; asm("rcp.approx.f32 %0, %1;" : "=f"(r) : "f"(t + 1.f));
    return (t - 1.f) * r;
}
__device__ __forceinline__ float warp_bfly(float v) {
    v += __shfl_xor_sync(0xffffffffu, v, 16);
    v += __shfl_xor_sync(0xffffffffu, v, 8);
    v += __shfl_xor_sync(0xffffffffu, v, 4);
    v += __shfl_xor_sync(0xffffffffu, v, 2);
    v += __shfl_xor_sync(0xffffffffu, v, 1);
    return v;
}
__device__ __forceinline__ unsigned ldv(unsigned* p) { return *((volatile unsigned*)p); }
__device__ __forceinline__ float d4(float4 a, float4 b) {
    return a.x * b.x + a.y * b.y + a.z * b.z + a.w * b.w;
}
// pack 4 floats -> 4 e4m3 (f0 in byte0)
__device__ __forceinline__ unsigned pack4_e4m3(float f0, float f1, float f2, float f3) {
    unsigned short lo, hi;
    asm("cvt.rn.satfinite.e4m3x2.f32 %0, %1, %2;" : "=h"(lo) : "f"(f1), "f"(f0));
    asm("cvt.rn.satfinite.e4m3x2.f32 %0, %1, %2;" : "=h"(hi) : "f"(f3), "f"(f2));
    return (unsigned)lo | ((unsigned)hi << 16);
}
// unpack 4 e4m3 (uint) -> two half2 (byte0 -> p0.lo)
#define UNPACK8(u, p0, p1) \
    asm("{.reg .b16 lo,hi; mov.b32 {lo,hi}, %2; cvt.rn.f16x2.e4m3x2 %0, lo; cvt.rn.f16x2.e4m3x2 %1, hi;}" \
        : "=r"(p0), "=r"(p1) : "r"(u))

// flag barrier: 1 fenced STG per block, 148 parallel pollers, monotonic tag.
__device__ __forceinline__ void fbar(int bid, int tid, unsigned tag) {
    __syncthreads();
    if (tid == 0) {
        __threadfence();
        ((volatile unsigned*)g_flags)[bid * 8] = tag;
    }
    if (tid < NB) {
        while (ldv(&g_flags[tid * 8]) < tag) { }
    }
    __syncthreads();
}

// ---------------- kA: transpose im -> fp16 imc; w1T; expC ----------------
__global__ void kA(const float* __restrict__ im, const float* __restrict__ w1,
                   const float* __restrict__ vw, const float* __restrict__ vb) {
    __shared__ float tile[32][33];
    int tx = threadIdx.x, ty = threadIdx.y;
    int l0 = blockIdx.x * 32, j0 = blockIdx.y * 32;
    int j = j0 + ty;
    if (j < S2) tile[ty][tx] = im[(size_t)j * LSEQ + l0 + tx];
    __syncthreads();
    int jw = j0 + tx;
    if (jw < S2)
        ((__half*)g_imc)[(size_t)(l0 + ty) * S2 + jw] = __float2half_rn(tile[tx][ty]);

    if (blockIdx.x == 0 && blockIdx.y == 0) {
        int tid = ty * 32 + tx;
        for (int i = tid; i < NS * S2; i += 1024) {
            int a = i / S2, jj = i - a * S2;
            g_w1T[jj * NS + a] = w1[i];
        }
        if (tid == 0) {
            float s = fabsf(vb[0]);
            for (int a = 0; a < NS; a++) s += fabsf(vw[a]);
            g_expC = s;
        }
    }
}

// ---------------- kB: w1dt tiles + fp8 conversions ----------------
__global__ void kB() {
    __shared__ __align__(16) float rows[32][200];
    __shared__ float souts[32][100];
    int tid = threadIdx.x;
    for (int tile = blockIdx.x; tile < NT; tile += gridDim.x) {
        const __half2* src = g_imc + (size_t)tile * 3200;
        for (int i = tid; i < 3200; i += 256) {
            int l = i / 100, j2 = i - l * 100;
            float2 f = __half22float2(src[i]);
            rows[l][2 * j2] = f.x;
            rows[l][2 * j2 + 1] = f.y;
        }
        __syncthreads();
        if (tid < NS) {
            #pragma unroll
            for (int p = 0; p < 4; p++) {
                float acc[8];
                #pragma unroll
                for (int li = 0; li < 8; li++) acc[li] = 0.f;
                for (int j = 0; j < 200; j += 4) {
                    float w0 = g_w1T[(j + 0) * NS + tid];
                    float w1v = g_w1T[(j + 1) * NS + tid];
                    float w2v = g_w1T[(j + 2) * NS + tid];
                    float w3v = g_w1T[(j + 3) * NS + tid];
                    #pragma unroll
                    for (int li = 0; li < 8; li++) {
                        float4 r = *(const float4*)&rows[p * 8 + li][j];
                        acc[li] += r.x * w0 + r.y * w1v + r.z * w2v + r.w * w3v;
                    }
                }
                #pragma unroll
                for (int li = 0; li < 8; li++) souts[p * 8 + li][tid] = acc[li];
            }
        }
        __syncthreads();
        // fp8 score tiles: [a4][lane]
        for (int i = tid; i < 800; i += 256) {
            int a4 = i >> 5, lane = i & 31;
            ((unsigned*)(g_w1t8 + (size_t)tile * 3200))[i] =
                pack4_e4m3(souts[lane][4 * a4], souts[lane][4 * a4 + 1],
                           souts[lane][4 * a4 + 2], souts[lane][4 * a4 + 3]);
        }
        // fp8 imc rows: [l][j]
        for (int i = tid; i < 1600; i += 256) {
            int l = i / 50, q = i - l * 50;
            ((unsigned*)(g_imc8 + (size_t)(tile * 32 + l) * 200))[q] =
                pack4_e4m3(rows[l][4 * q], rows[l][4 * q + 1],
                           rows[l][4 * q + 2], rows[l][4 * q + 3]);
        }
        __syncthreads();
    }
}

// kD: zero ctx buffers + flags (per-launch, in-graph so replay-safe)
__global__ void kD() {
    int i = threadIdx.x;
    if (i < 256) { g_ctxbuf[0][i] = 0.f; g_ctxbuf[1][i] = 0.f; }
    for (int k = i; k < NB * 8; k += 512) g_flags[k] = 0u;
}

// ---------------- persistent main kernel ----------------
__global__ void __launch_bounds__(512, 1) k_main(
    const int*   __restrict__ ids,
    const float* __restrict__ Wih,  const float* __restrict__ Whh,
    const float* __restrict__ bih,  const float* __restrict__ bhh,
    const float* __restrict__ w2,
    const float* __restrict__ vw,   const float* __restrict__ vb,
    const float* __restrict__ linw, const float* __restrict__ linb,
    const float* __restrict__ emb,  const int* __restrict__ eosp,
    float* __restrict__ out, int T)
{
    const int tid  = threadIdx.x, lane = tid & 31, wid = tid >> 5;
    const int bid  = blockIdx.x;
    const int start = (bid * NT) / NB;
    const int cnt   = ((bid + 1) * NT) / NB - start;

    extern __shared__ __align__(16) char dynsm[];
    char*     s_imc8 = dynsm + OFF_IMC8;                     // [MAXT][6400] fp8
    unsigned* s_w18  = (unsigned*)(dynsm + OFF_W18);         // [MAXT][25][32] packed fp8
    __half2*  s_w2hT = (__half2*)(dynsm + OFF_W2HT);         // [100][100] j2-major
    unsigned* s_wh2  = (unsigned*)(dynsm + OFF_WH2);         // [16][104] half2 partials

    __shared__ unsigned s_e2[16 * 33];       // half2(e,e) per l
    __shared__ float s_wz[16];
    __shared__ __align__(16) float s_vv[NS];
    __shared__ __align__(16) __half s_wdhH[112];
    __shared__ __align__(16) __half2 s_hc2[112];
    __shared__ __align__(16) float s_h[NS];
    __shared__ __align__(16) float s_g[G4];
    __shared__ __align__(16) float s_emb[NS];
    __shared__ __align__(16) float s_ctx[208];
    __shared__ float s_d0[4];
    __shared__ float s_loss;

    const float vb0  = vb[0];
    const float Moff = g_expC;
    const int   eos  = eosp ? *eosp : 0;

    float rc0 = 0.f, rc1 = 0.f;   // register-carried cell state (thread tid<50 owns 2 states)

    // ---- one-time init ----
    {
        const float4* s0 = (const float4*)(g_imc8 + (size_t)start * 6400);
        for (int i = tid; i < cnt * 400; i += 512) ((float4*)s_imc8)[i] = s0[i];
        const float4* s1 = (const float4*)(g_w1t8 + (size_t)start * 3200);
        for (int i = tid; i < cnt * 200; i += 512) ((float4*)s_w18)[i] = s1[i];
        for (int i = tid; i < 16 * 104; i += 512) s_wh2[i] = 0u;
        for (int i = tid; i < 10000; i += 512) {
            int j2 = i / 100, a = i - j2 * 100;
            s_w2hT[j2 * 100 + a] =
                __floats2half2_rn(__ldg(&w2[a * S2 + 2 * j2]), __ldg(&w2[a * S2 + 2 * j2 + 1]));
        }
        if (tid < NS) s_vv[tid] = vw[tid];
        if (tid < 16) s_wz[tid] = 0.f;
        if (bid == 1 && tid == 0) s_loss = 0.f;
    }
    __syncthreads();

    for (int t = 0; t <= T; t++) {
        // ================= PHASE_E: redundant epilogue (every block) =================
        int prev = (t == 0) ? eos : __ldg(&ids[t - 1]);
        if (t == 0) {
            if (tid < G4) {
                const float4* wr = (const float4*)(Wih + tid * XD + S2);
                const float4* ev = (const float4*)(emb + eos * NS);
                float acc = __ldg(&bih[tid]) + __ldg(&bhh[tid]);
                #pragma unroll
                for (int i = 0; i < 25; i++) acc += d4(__ldg(wr + i), __ldg(ev + i));
                s_g[tid] = acc;
            }
        }
        // emb prefetch for this step's gates (threads 400-499 idle in E)
        if (tid >= 400 && tid < 500) s_emb[tid - 400] = __ldg(&emb[prev * NS + tid - 400]);
        // zero own slice of next-parity ctx buffer (reader G(t-1) done at W2(t-1))
        if (tid == 500) {
            g_ctxbuf[(t + 1) & 1][bid] = 0.f;
            if (bid + NB <= 200) g_ctxbuf[(t + 1) & 1][bid + NB] = 0.f;
        }
        if (t == 0) __syncthreads();          // s_g ready for priming
        if (tid < 50) {
            float2 gi, gf, gg, go;
            if (t == 0) {
                gi = *(const float2*)&s_g[2 * tid];
                gf = *(const float2*)&s_g[100 + 2 * tid];
                gg = *(const float2*)&s_g[200 + 2 * tid];
                go = *(const float2*)&s_g[300 + 2 * tid];
            } else {
                gi = __ldcg((const float2*)g_gate + tid);
                gf = __ldcg((const float2*)g_gate + 50 + tid);
                gg = __ldcg((const float2*)g_gate + 100 + tid);
                go = __ldcg((const float2*)g_gate + 150 + tid);
            }
            float cn0 = sigf(gf.x) * rc0 + sigf(gi.x) * tanh_acc(gg.x);
            float cn1 = sigf(gf.y) * rc1 + sigf(gi.y) * tanh_acc(gg.y);
            rc0 = cn0; rc1 = cn1;
            float h0 = sigf(go.x) * tanh_acc(cn0);
            float h1 = sigf(go.y) * tanh_acc(cn1);
            s_h[2 * tid] = h0; s_h[2 * tid + 1] = h1;
            s_hc2[tid]      = __floats2half2_rn(h0, h1);
            s_hc2[50 + tid] = __floats2half2_rn(cn0, cn1);
        }
        __syncthreads();
        if (tid < NS) {
            __half2 accA = __floats2half2_rn(0.f, 0.f);
            __half2 accB = __floats2half2_rn(0.f, 0.f);
            const __half2* wt = s_w2hT + tid;
            #pragma unroll 10
            for (int j2 = 0; j2 < 100; j2 += 2) {
                accA = __hfma2(wt[j2 * 100], s_hc2[j2], accA);
                accB = __hfma2(wt[(j2 + 1) * 100], s_hc2[j2 + 1], accB);
            }
            __half2 acc2 = __hadd2(accA, accB);
            s_wdhH[tid] = __hadd(__low2half(acc2), __high2half(acc2));
        }
        __syncthreads();

        // ---- loss for step t-1 (block 1 spare warp, local s_h) ----
        if (bid == 1 && wid == 15 && t > 0) {
            int ch = __ldg(&ids[t - 1]);
            float lg[4];
            #pragma unroll
            for (int k = 0; k < 4; k++) {
                int row = lane + 32 * k;
                const float4* lr = (const float4*)(linw + row * NS);
                const float4* hv = (const float4*)s_h;
                float acc = __ldg(&linb[row]);
                #pragma unroll
                for (int i = 0; i < 25; i++) acc += d4(__ldg(lr + i), hv[i]);
                lg[k] = acc;
            }
            float m = fmaxf(fmaxf(lg[0], lg[1]), fmaxf(lg[2], lg[3]));
            m = fmaxf(m, __shfl_xor_sync(0xffffffffu, m, 16));
            m = fmaxf(m, __shfl_xor_sync(0xffffffffu, m, 8));
            m = fmaxf(m, __shfl_xor_sync(0xffffffffu, m, 4));
            m = fmaxf(m, __shfl_xor_sync(0xffffffffu, m, 2));
            m = fmaxf(m, __shfl_xor_sync(0xffffffffu, m, 1));
            float se = expf(lg[0] - m) + expf(lg[1] - m) + expf(lg[2] - m) + expf(lg[3] - m);
            se = warp_bfly(se);
            float tg = 0.f;
            #pragma unroll
            for (int k = 0; k < 4; k++) if (lane + 32 * k == ch) tg = lg[k];
            tg = warp_bfly(tg);
            if (lane == 0) s_loss += logf(se) + m - tg;
            if (t == T && lane == 0) out[0] = s_loss;
        }
        if (t == T) break;

        // ================= PHASE_A: attention (all smem-resident) =================
        const __half2* s_wdh = (const __half2*)s_wdhH;
        if (wid < cnt) {
            const int lt = wid;
            const unsigned* wt8 = s_w18 + lt * 800 + lane;
            float sc = 0.f;
            #pragma unroll
            for (int a4 = 0; a4 < 25; a4++) {
                unsigned u = wt8[a4 * 32];
                unsigned p0, p1;
                UNPACK8(u, p0, p1);
                __half2 t0 = tanh2(__hadd2(*(__half2*)&p0, s_wdh[2 * a4]));
                __half2 t1 = tanh2(__hadd2(*(__half2*)&p1, s_wdh[2 * a4 + 1]));
                float2 f0 = __half22float2(t0), f1 = __half22float2(t1);
                float4 vvq = *(const float4*)&s_vv[4 * a4];
                sc += vvq.x * f0.x + vvq.y * f0.y + vvq.z * f1.x + vvq.w * f1.y;
            }
            float e = ex2fast((sc + vb0 - Moff) * LOG2E);
            {
                __half eh = __float2half_rn(e);
                __half2 e2 = __half2half2(eh);
                s_e2[wid * 33 + lane] = *(unsigned*)&e2;
            }
            __syncwarp();

            if (lane < 25) {
                __half2 acc2[4];
                #pragma unroll
                for (int i = 0; i < 4; i++) acc2[i] = __floats2half2_rn(0.f, 0.f);
                const uint2* ib = (const uint2*)(s_imc8 + lt * 6400) + lane;
                const unsigned* ep = s_e2 + wid * 33;
                #pragma unroll 8
                for (int li = 0; li < 32; li++) {
                    uint2 v = ib[li * 25];
                    unsigned eu = ep[li];
                    __half2 e2 = *(__half2*)&eu;
                    unsigned p0, p1, p2, p3;
                    UNPACK8(v.x, p0, p1);
                    UNPACK8(v.y, p2, p3);
                    acc2[0] = __hfma2(*(__half2*)&p0, e2, acc2[0]);
                    acc2[1] = __hfma2(*(__half2*)&p1, e2, acc2[1]);
                    acc2[2] = __hfma2(*(__half2*)&p2, e2, acc2[2]);
                    acc2[3] = __hfma2(*(__half2*)&p3, e2, acc2[3]);
                }
                uint4 st;
                st.x = *(unsigned*)&acc2[0]; st.y = *(unsigned*)&acc2[1];
                st.z = *(unsigned*)&acc2[2]; st.w = *(unsigned*)&acc2[3];
                *(uint4*)&s_wh2[wid * 104 + lane * 4] = st;
            }
            float z = warp_bfly(e);
            if (lane == 0) s_wz[wid] = z;
        }
        __syncthreads();
        if (tid < 100) {
            float sx = 0.f, sy = 0.f;
            #pragma unroll
            for (int w = 0; w < 16; w++) {
                unsigned u = s_wh2[w * 104 + tid];
                float2 f = __half22float2(*(__half2*)&u);
                sx += f.x; sy += f.y;
            }
            atomicAdd(&g_ctxbuf[t & 1][2 * tid], sx);
            atomicAdd(&g_ctxbuf[t & 1][2 * tid + 1], sy);
        }
        if (tid == 256) {
            float s = 0.f;
            #pragma unroll
            for (int w = 0; w < 16; w++) s += s_wz[w];
            atomicAdd(&g_ctxbuf[t & 1][200], s);
        }
        // ---- warp 15: constant part of this block's gates (overlaps atomics/W1) ----
        if (wid == 15) {
            #pragma unroll
            for (int g = 0; g < 3; g++) {
                int k = g * NB + bid;
                if (k < G4) {
                    float d0 = 0.f;
                    if (lane < 25) {
                        const float4* wr = (const float4*)(Wih + k * XD);
                        d0 = d4(__ldg(wr + 50 + lane), ((const float4*)s_emb)[lane]);
                        const float4* hr = (const float4*)(Whh + k * NS);
                        d0 += d4(__ldg(hr + lane), ((const float4*)s_h)[lane]);
                    }
                    d0 = warp_bfly(d0);
                    if (lane == 0)
                        s_d0[g] = d0 + __ldg(&bih[k]) + __ldg(&bhh[k]);
                }
            }
        }

        fbar(bid, tid, 2u * (unsigned)t + 1u);      // W1: ctx(t) complete

        // ================= PHASE_G: gates (ctx part only; 3 per block) =================
        if (tid < 201) s_ctx[tid] = __ldcg(&g_ctxbuf[t & 1][tid]);
        __syncthreads();
        if (wid < 3) {
            int k = wid * NB + bid;
            if (k < G4) {
                float rz = 1.f / s_ctx[200];
                float dc = 0.f;
                if (lane < 25) {
                    const float4* wr = (const float4*)(Wih + k * XD);
                    const float4* cx = (const float4*)s_ctx;
                    dc = d4(__ldg(wr + 2 * lane), cx[2 * lane])
                       + d4(__ldg(wr + 2 * lane + 1), cx[2 * lane + 1]);
                }
                dc = warp_bfly(dc);
                if (lane == 0)
                    g_gate[k] = dc * rz + s_d0[wid];
            }
        }
        fbar(bid, tid, 2u * (unsigned)t + 2u);      // W2: gates(t) visible
    }
}

// ---------------- launch ----------------
extern "C" void kernel_launch(void* const* d_in, const int* in_sizes, int n_in,
                              void* d_out, int out_size) {
    const float* im   = (const float*)d_in[0];
    const int*   ids  = (const int*)  d_in[1];
    const float* Wih  = (const float*)d_in[2];
    const float* Whh  = (const float*)d_in[3];
    const float* bih  = (const float*)d_in[4];
    const float* bhh  = (const float*)d_in[5];
    const float* w1   = (const float*)d_in[6];
    const float* w2   = (const float*)d_in[7];
    const float* vw   = (const float*)d_in[8];
    const float* vb   = (const float*)d_in[9];
    const float* linw = (const float*)d_in[10];
    const float* linb = (const float*)d_in[11];
    const float* emb  = (const float*)d_in[12];
    const int*   eosp = (n_in > 13) ? (const int*)d_in[13] : nullptr;
    const int T = in_sizes[1];

    cudaFuncSetAttribute(k_main, cudaFuncAttributeMaxDynamicSharedMemorySize, DYN_SZ);

    kA<<<dim3(LSEQ / 32, 7), dim3(32, 32)>>>(im, w1, vw, vb);
    kB<<<512, 256>>>();
    kD<<<1, 512>>>();
    k_main<<<NB, 512, DYN_SZ>>>(ids, Wih, Whh, bih, bhh, w2, vw, vb, linw, linb,
                                emb, eosp, (float*)d_out, T);
}

// round 16
// speedup vs baseline: 1.1203x; 1.1203x over previous
#include <cuda_runtime.h>
#include <cuda_fp16.h>
#include <math.h>

#define LSEQ 65536
#define NS   100
#define S2   200
#define XD   300
#define G4   400
#define NV   128
#define NB   148
#define NT   2048
#define MAXT 14
#define LOG2E 1.4426950408889634f

// dynamic smem layout (bytes)
#define OFF_IMC8 0
#define OFF_W18  (MAXT * 6400)                 // 89600
#define OFF_W2HT (OFF_W18 + MAXT * 3200)       // 134400
#define OFF_WH2  (OFF_W2HT + 40000)            // 174400
#define DYN_SZ   (OFF_WH2 + 16 * 104 * 4)      // 181056

// ---------------- device scratch ----------------
__device__ __align__(128) __half2 g_imc [LSEQ * 100];        // fp16 [l][j2] (precompute input)
__device__ __align__(128) unsigned char g_imc8[LSEQ * 200];  // fp8 [l][j]
__device__ __align__(128) unsigned char g_w1t8[NT * 3200];   // fp8 [tile][a4][lane] uints
__device__ float g_w1T[S2 * NS];
__device__ float g_expC;
__device__ __align__(16) float g_ctxbuf[2][256];             // double-buffered; [200]=Z
__device__ __align__(16) float g_gate[G4];
__device__ __align__(128) unsigned g_flags[NB * 8];          // monotonic wave tags
__device__ unsigned g_rsvd;

// ---------------- helpers ----------------
__device__ __forceinline__ float ex2fast(float x) {
    float y; asm("ex2.approx.f32 %0, %1;" : "=f"(y) : "f"(x)); return y;
}
__device__ __forceinline__ __half2 tanh2(__half2 x) {
    unsigned xi = *(unsigned*)&x, yi;
    asm("tanh.approx.f16x2 %0, %1;" : "=r"(yi) : "r"(xi));
    return *(__half2*)&yi;
}
__device__ __forceinline__ float sigf(float x) {
    float t; asm("ex2.approx.f32 %0, %1;" : "=f"(t) : "f"(-x * LOG2E));
    float r; asm("rcp.approx.f32 %0, %1;" : "=f"(r) : "f"(1.f + t));
    return r;
}
__device__ __forceinline__ float tanh_acc(float x) {
    x = fminf(10.f, fmaxf(-10.f, x));
    float t; asm("ex2.approx.f32 %0, %1;" : "=f"(t) : "f"(x * 2.885390081777927f));
    float r; asm("rcp.approx.f32 %0, %1;" : "=f"(r) : "f"(t + 1.f));
    return (t - 1.f) * r;
}
__device__ __forceinline__ float warp_bfly(float v) {
    v += __shfl_xor_sync(0xffffffffu, v, 16);
    v += __shfl_xor_sync(0xffffffffu, v, 8);
    v += __shfl_xor_sync(0xffffffffu, v, 4);
    v += __shfl_xor_sync(0xffffffffu, v, 2);
    v += __shfl_xor_sync(0xffffffffu, v, 1);
    return v;
}
__device__ __forceinline__ unsigned ldv(unsigned* p) { return *((volatile unsigned*)p); }
__device__ __forceinline__ float d4(float4 a, float4 b) {
    return a.x * b.x + a.y * b.y + a.z * b.z + a.w * b.w;
}
// pack 4 floats -> 4 e4m3 (f0 in byte0)
__device__ __forceinline__ unsigned pack4_e4m3(float f0, float f1, float f2, float f3) {
    unsigned short lo, hi;
    asm("cvt.rn.satfinite.e4m3x2.f32 %0, %1, %2;" : "=h"(lo) : "f"(f1), "f"(f0));
    asm("cvt.rn.satfinite.e4m3x2.f32 %0, %1, %2;" : "=h"(hi) : "f"(f3), "f"(f2));
    return (unsigned)lo | ((unsigned)hi << 16);
}
// unpack 4 e4m3 (uint) -> two half2 (byte0 -> p0.lo)
#define UNPACK8(u, p0, p1) \
    asm("{.reg .b16 lo,hi; mov.b32 {lo,hi}, %2; cvt.rn.f16x2.e4m3x2 %0, lo; cvt.rn.f16x2.e4m3x2 %1, hi;}" \
        : "=r"(p0), "=r"(p1) : "r"(u))

// flag barrier: 1 fenced STG per block, 148 parallel pollers, monotonic tag.
__device__ __forceinline__ void fbar(int bid, int tid, unsigned tag) {
    __syncthreads();
    if (tid == 0) {
        __threadfence();
        ((volatile unsigned*)g_flags)[bid * 8] = tag;
    }
    if (tid < NB) {
        while (ldv(&g_flags[tid * 8]) < tag) { }
    }
    __syncthreads();
}

// ---------------- kA: transpose im -> fp16 imc; w1T; expC ----------------
__global__ void kA(const float* __restrict__ im, const float* __restrict__ w1,
                   const float* __restrict__ vw, const float* __restrict__ vb) {
    __shared__ float tile[32][33];
    int tx = threadIdx.x, ty = threadIdx.y;
    int l0 = blockIdx.x * 32, j0 = blockIdx.y * 32;
    int j = j0 + ty;
    if (j < S2) tile[ty][tx] = im[(size_t)j * LSEQ + l0 + tx];
    __syncthreads();
    int jw = j0 + tx;
    if (jw < S2)
        ((__half*)g_imc)[(size_t)(l0 + ty) * S2 + jw] = __float2half_rn(tile[tx][ty]);

    if (blockIdx.x == 0 && blockIdx.y == 0) {
        int tid = ty * 32 + tx;
        for (int i = tid; i < NS * S2; i += 1024) {
            int a = i / S2, jj = i - a * S2;
            g_w1T[jj * NS + a] = w1[i];
        }
        if (tid == 0) {
            float s = fabsf(vb[0]);
            for (int a = 0; a < NS; a++) s += fabsf(vw[a]);
            g_expC = s;
        }
    }
}

// ---------------- kB: w1dt tiles + fp8 conversions ----------------
__global__ void kB() {
    __shared__ __align__(16) float rows[32][200];
    __shared__ float souts[32][100];
    int tid = threadIdx.x;
    for (int tile = blockIdx.x; tile < NT; tile += gridDim.x) {
        const __half2* src = g_imc + (size_t)tile * 3200;
        for (int i = tid; i < 3200; i += 256) {
            int l = i / 100, j2 = i - l * 100;
            float2 f = __half22float2(src[i]);
            rows[l][2 * j2] = f.x;
            rows[l][2 * j2 + 1] = f.y;
        }
        __syncthreads();
        if (tid < NS) {
            #pragma unroll
            for (int p = 0; p < 4; p++) {
                float acc[8];
                #pragma unroll
                for (int li = 0; li < 8; li++) acc[li] = 0.f;
                for (int j = 0; j < 200; j += 4) {
                    float w0 = g_w1T[(j + 0) * NS + tid];
                    float w1v = g_w1T[(j + 1) * NS + tid];
                    float w2v = g_w1T[(j + 2) * NS + tid];
                    float w3v = g_w1T[(j + 3) * NS + tid];
                    #pragma unroll
                    for (int li = 0; li < 8; li++) {
                        float4 r = *(const float4*)&rows[p * 8 + li][j];
                        acc[li] += r.x * w0 + r.y * w1v + r.z * w2v + r.w * w3v;
                    }
                }
                #pragma unroll
                for (int li = 0; li < 8; li++) souts[p * 8 + li][tid] = acc[li];
            }
        }
        __syncthreads();
        // fp8 score tiles: [a4][lane]
        for (int i = tid; i < 800; i += 256) {
            int a4 = i >> 5, lane = i & 31;
            ((unsigned*)(g_w1t8 + (size_t)tile * 3200))[i] =
                pack4_e4m3(souts[lane][4 * a4], souts[lane][4 * a4 + 1],
                           souts[lane][4 * a4 + 2], souts[lane][4 * a4 + 3]);
        }
        // fp8 imc rows: [l][j]
        for (int i = tid; i < 1600; i += 256) {
            int l = i / 50, q = i - l * 50;
            ((unsigned*)(g_imc8 + (size_t)(tile * 32 + l) * 200))[q] =
                pack4_e4m3(rows[l][4 * q], rows[l][4 * q + 1],
                           rows[l][4 * q + 2], rows[l][4 * q + 3]);
        }
        __syncthreads();
    }
}

// kD: zero ctx buffers + flags (per-launch, in-graph so replay-safe)
__global__ void kD() {
    int i = threadIdx.x;
    if (i < 256) { g_ctxbuf[0][i] = 0.f; g_ctxbuf[1][i] = 0.f; }
    for (int k = i; k < NB * 8; k += 512) g_flags[k] = 0u;
}

// ---------------- persistent main kernel ----------------
__global__ void __launch_bounds__(512, 1) k_main(
    const int*   __restrict__ ids,
    const float* __restrict__ Wih,  const float* __restrict__ Whh,
    const float* __restrict__ bih,  const float* __restrict__ bhh,
    const float* __restrict__ w2,
    const float* __restrict__ vw,   const float* __restrict__ vb,
    const float* __restrict__ linw, const float* __restrict__ linb,
    const float* __restrict__ emb,  const int* __restrict__ eosp,
    float* __restrict__ out, int T)
{
    const int tid  = threadIdx.x, lane = tid & 31, wid = tid >> 5;
    const int bid  = blockIdx.x;
    const int start = (bid * NT) / NB;
    const int cnt   = ((bid + 1) * NT) / NB - start;

    extern __shared__ __align__(16) char dynsm[];
    char*     s_imc8 = dynsm + OFF_IMC8;                     // [MAXT][6400] fp8
    unsigned* s_w18  = (unsigned*)(dynsm + OFF_W18);         // [MAXT][25][32] packed fp8
    __half2*  s_w2hT = (__half2*)(dynsm + OFF_W2HT);         // [100][100] j2-major
    unsigned* s_wh2  = (unsigned*)(dynsm + OFF_WH2);         // [16][104] half2 partials

    __shared__ unsigned s_e2[16 * 33];       // half2(e,e) per l
    __shared__ float s_wz[16];
    __shared__ __align__(16) float s_vv[NS];
    __shared__ __align__(16) __half s_wdhH[112];
    __shared__ __align__(16) __half2 s_hc2[112];
    __shared__ __align__(16) float s_h[NS];
    __shared__ __align__(16) float s_c[NS];
    __shared__ __align__(16) float s_g[G4];
    __shared__ __align__(16) float s_emb[NS];
    __shared__ float s_d0[4];
    __shared__ float s_loss;

    const float vb0  = vb[0];
    const float Moff = g_expC;
    const int   eos  = eosp ? *eosp : 0;

    // ---- one-time init ----
    {
        const float4* s0 = (const float4*)(g_imc8 + (size_t)start * 6400);
        for (int i = tid; i < cnt * 400; i += 512) ((float4*)s_imc8)[i] = s0[i];
        const float4* s1 = (const float4*)(g_w1t8 + (size_t)start * 3200);
        for (int i = tid; i < cnt * 200; i += 512) ((float4*)s_w18)[i] = s1[i];
        for (int i = tid; i < 16 * 104; i += 512) s_wh2[i] = 0u;
        for (int i = tid; i < 10000; i += 512) {
            int j2 = i / 100, a = i - j2 * 100;
            s_w2hT[j2 * 100 + a] =
                __floats2half2_rn(__ldg(&w2[a * S2 + 2 * j2]), __ldg(&w2[a * S2 + 2 * j2 + 1]));
        }
        if (tid < NS) s_vv[tid] = vw[tid];
        if (tid < 16) s_wz[tid] = 0.f;
        if (bid == 1 && tid == 0) s_loss = 0.f;
    }
    __syncthreads();

    for (int t = 0; t <= T; t++) {
        // ================= PHASE_E: redundant epilogue (every block) =================
        if (t == 0) {
            if (tid < G4) {
                const float4* wr = (const float4*)(Wih + tid * XD + S2);
                const float4* ev = (const float4*)(emb + eos * NS);
                float acc = __ldg(&bih[tid]) + __ldg(&bhh[tid]);
                #pragma unroll
                for (int i = 0; i < 25; i++) acc += d4(__ldg(wr + i), __ldg(ev + i));
                s_g[tid] = acc;
            }
        } else {
            if (tid < G4) s_g[tid] = __ldcg(&g_gate[tid]);
        }
        // emb(prev) prefetch for this step's d0 (threads 400-499 idle in E)
        if (tid >= 400 && tid < 500) {
            int prev = (t == 0) ? eos : __ldg(&ids[t - 1]);
            s_emb[tid - 400] = __ldg(&emb[prev * NS + tid - 400]);
        }
        // zero own slice of next-parity ctx buffer (reader G(t-1) done at W2(t-1))
        if (tid == 380) {
            g_ctxbuf[(t + 1) & 1][bid] = 0.f;
            if (bid + NB <= 200) g_ctxbuf[(t + 1) & 1][bid + NB] = 0.f;
        }
        __syncthreads();
        if (tid < NS) {
            float gi = s_g[tid], gf = s_g[NS + tid];
            float gg = s_g[2 * NS + tid], go = s_g[3 * NS + tid];
            float cprev = (t == 0) ? 0.f : s_c[tid];
            float cn = sigf(gf) * cprev + sigf(gi) * tanh_acc(gg);
            s_c[tid] = cn;
            s_h[tid] = sigf(go) * tanh_acc(cn);
        }
        __syncthreads();
        if (tid < 50) s_hc2[tid] = __floats2half2_rn(s_h[2 * tid], s_h[2 * tid + 1]);
        else if (tid >= 64 && tid < 114) {
            int q = tid - 64;
            s_hc2[50 + q] = __floats2half2_rn(s_c[2 * q], s_c[2 * q + 1]);
        }
        __syncthreads();
        if (tid < NS) {
            __half2 accA = __floats2half2_rn(0.f, 0.f);
            __half2 accB = __floats2half2_rn(0.f, 0.f);
            const __half2* wt = s_w2hT + tid;
            #pragma unroll 10
            for (int j2 = 0; j2 < 100; j2 += 2) {
                accA = __hfma2(wt[j2 * 100], s_hc2[j2], accA);
                accB = __hfma2(wt[(j2 + 1) * 100], s_hc2[j2 + 1], accB);
            }
            __half2 acc2 = __hadd2(accA, accB);
            s_wdhH[tid] = __hadd(__low2half(acc2), __high2half(acc2));
        }
        __syncthreads();

        // ---- loss for step t-1 (block 1 spare warp, local s_h) ----
        if (bid == 1 && wid == 15 && t > 0) {
            int ch = __ldg(&ids[t - 1]);
            float lg[4];
            #pragma unroll
            for (int k = 0; k < 4; k++) {
                int row = lane + 32 * k;
                const float4* lr = (const float4*)(linw + row * NS);
                const float4* hv = (const float4*)s_h;
                float acc = __ldg(&linb[row]);
                #pragma unroll
                for (int i = 0; i < 25; i++) acc += d4(__ldg(lr + i), hv[i]);
                lg[k] = acc;
            }
            float m = fmaxf(fmaxf(lg[0], lg[1]), fmaxf(lg[2], lg[3]));
            m = fmaxf(m, __shfl_xor_sync(0xffffffffu, m, 16));
            m = fmaxf(m, __shfl_xor_sync(0xffffffffu, m, 8));
            m = fmaxf(m, __shfl_xor_sync(0xffffffffu, m, 4));
            m = fmaxf(m, __shfl_xor_sync(0xffffffffu, m, 2));
            m = fmaxf(m, __shfl_xor_sync(0xffffffffu, m, 1));
            float se = expf(lg[0] - m) + expf(lg[1] - m) + expf(lg[2] - m) + expf(lg[3] - m);
            se = warp_bfly(se);
            float tg = 0.f;
            #pragma unroll
            for (int k = 0; k < 4; k++) if (lane + 32 * k == ch) tg = lg[k];
            tg = warp_bfly(tg);
            if (lane == 0) s_loss += logf(se) + m - tg;
            if (t == T && lane == 0) out[0] = s_loss;
        }
        if (t == T) break;

        // ================= PHASE_A: attention + overlapped d0 (idle warps) =========
        const __half2* s_wdh = (const __half2*)s_wdhH;
        if (wid < cnt) {
            const int lt = wid;
            const unsigned* wt8 = s_w18 + lt * 800 + lane;
            float sc = 0.f;
            #pragma unroll
            for (int a4 = 0; a4 < 25; a4++) {
                unsigned u = wt8[a4 * 32];
                unsigned p0, p1;
                UNPACK8(u, p0, p1);
                __half2 t0 = tanh2(__hadd2(*(__half2*)&p0, s_wdh[2 * a4]));
                __half2 t1 = tanh2(__hadd2(*(__half2*)&p1, s_wdh[2 * a4 + 1]));
                float2 f0 = __half22float2(t0), f1 = __half22float2(t1);
                float4 vvq = *(const float4*)&s_vv[4 * a4];
                sc += vvq.x * f0.x + vvq.y * f0.y + vvq.z * f1.x + vvq.w * f1.y;
            }
            float e = ex2fast((sc + vb0 - Moff) * LOG2E);
            {
                __half eh = __float2half_rn(e);
                __half2 e2 = __half2half2(eh);
                s_e2[wid * 33 + lane] = *(unsigned*)&e2;
            }
            __syncwarp();

            if (lane < 25) {
                __half2 acc2[4];
                #pragma unroll
                for (int i = 0; i < 4; i++) acc2[i] = __floats2half2_rn(0.f, 0.f);
                const uint2* ib = (const uint2*)(s_imc8 + lt * 6400) + lane;
                const unsigned* ep = s_e2 + wid * 33;
                #pragma unroll 8
                for (int li = 0; li < 32; li++) {
                    uint2 v = ib[li * 25];
                    unsigned eu = ep[li];
                    __half2 e2 = *(__half2*)&eu;
                    unsigned p0, p1, p2, p3;
                    UNPACK8(v.x, p0, p1);
                    UNPACK8(v.y, p2, p3);
                    acc2[0] = __hfma2(*(__half2*)&p0, e2, acc2[0]);
                    acc2[1] = __hfma2(*(__half2*)&p1, e2, acc2[1]);
                    acc2[2] = __hfma2(*(__half2*)&p2, e2, acc2[2]);
                    acc2[3] = __hfma2(*(__half2*)&p3, e2, acc2[3]);
                }
                uint4 st;
                st.x = *(unsigned*)&acc2[0]; st.y = *(unsigned*)&acc2[1];
                st.z = *(unsigned*)&acc2[2]; st.w = *(unsigned*)&acc2[3];
                *(uint4*)&s_wh2[wid * 104 + lane * 4] = st;
            }
            float z = warp_bfly(e);
            if (lane == 0) s_wz[wid] = z;
        } else if (wid >= 14) {
            // gate-constant part (emb + Whh·h + biases); cnt <= 14 so warps 14,15
            // are NEVER attention warps -> this fully overlaps PHASE_A.
            int gA = (wid == 14) ? 0 : 2;
            int gB = (wid == 14) ? 1 : 2;
            for (int g = gA; g <= gB; g++) {
                int k = g * NB + bid;
                if (k < G4) {
                    float d0 = 0.f;
                    if (lane < 25) {
                        const float4* wr = (const float4*)(Wih + k * XD);
                        d0 = d4(__ldg(wr + 50 + lane), ((const float4*)s_emb)[lane]);
                        const float4* hr = (const float4*)(Whh + k * NS);
                        d0 += d4(__ldg(hr + lane), ((const float4*)s_h)[lane]);
                    }
                    d0 = warp_bfly(d0);
                    if (lane == 0)
                        s_d0[g] = d0 + __ldg(&bih[k]) + __ldg(&bhh[k]);
                }
            }
        }
        __syncthreads();
        if (tid < 100) {
            float sx = 0.f, sy = 0.f;
            #pragma unroll
            for (int w = 0; w < 16; w++) {
                unsigned u = s_wh2[w * 104 + tid];
                float2 f = __half22float2(*(__half2*)&u);
                sx += f.x; sy += f.y;
            }
            atomicAdd(&g_ctxbuf[t & 1][2 * tid], sx);
            atomicAdd(&g_ctxbuf[t & 1][2 * tid + 1], sy);
        }
        if (tid == 256) {
            float s = 0.f;
            #pragma unroll
            for (int w = 0; w < 16; w++) s += s_wz[w];
            atomicAdd(&g_ctxbuf[t & 1][200], s);
        }

        fbar(bid, tid, 2u * (unsigned)t + 1u);      // W1: ctx(t) complete

        // ================= PHASE_G: ctx dot only (direct L2 loads, no staging) ======
        if (wid < 3) {
            int k = wid * NB + bid;
            if (k < G4) {
                float zv = __ldcg(&g_ctxbuf[t & 1][200]);
                float dc = 0.f;
                if (lane < 25) {
                    const float4* cb = (const float4*)g_ctxbuf[t & 1];
                    float4 c0 = __ldcg(cb + 2 * lane);
                    float4 c1 = __ldcg(cb + 2 * lane + 1);
                    const float4* wr = (const float4*)(Wih + k * XD);
                    dc = d4(__ldg(wr + 2 * lane), c0) + d4(__ldg(wr + 2 * lane + 1), c1);
                }
                dc = warp_bfly(dc);
                if (lane == 0)
                    g_gate[k] = dc * (1.f / zv) + s_d0[wid];
            }
        }
        fbar(bid, tid, 2u * (unsigned)t + 2u);      // W2: gates(t) visible
    }
}

// ---------------- launch ----------------
extern "C" void kernel_launch(void* const* d_in, const int* in_sizes, int n_in,
                              void* d_out, int out_size) {
    const float* im   = (const float*)d_in[0];
    const int*   ids  = (const int*)  d_in[1];
    const float* Wih  = (const float*)d_in[2];
    const float* Whh  = (const float*)d_in[3];
    const float* bih  = (const float*)d_in[4];
    const float* bhh  = (const float*)d_in[5];
    const float* w1   = (const float*)d_in[6];
    const float* w2   = (const float*)d_in[7];
    const float* vw   = (const float*)d_in[8];
    const float* vb   = (const float*)d_in[9];
    const float* linw = (const float*)d_in[10];
    const float* linb = (const float*)d_in[11];
    const float* emb  = (const float*)d_in[12];
    const int*   eosp = (n_in > 13) ? (const int*)d_in[13] : nullptr;
    const int T = in_sizes[1];

    cudaFuncSetAttribute(k_main, cudaFuncAttributeMaxDynamicSharedMemorySize, DYN_SZ);

    kA<<<dim3(LSEQ / 32, 7), dim3(32, 32)>>>(im, w1, vw, vb);
    kB<<<512, 256>>>();
    kD<<<1, 512>>>();
    k_main<<<NB, 512, DYN_SZ>>>(ids, Wih, Whh, bih, bhh, w2, vw, vb, linw, linb,
                                emb, eosp, (float*)d_out, T);
}